// round 1
// baseline (speedup 1.0000x reference)
#include <cuda_runtime.h>

// SinusoidPositionEncoding: out[b,s,:] = sum_m x[b,s,m] * pe[m,:]
// x is one-hot over m (4096), so this is a sparse gather-scale.
// Shapes: x (8,2048,4096) f32, pe (4096,128) f32, out (8,2048,128) f32.
//
// Strategy: 1 warp per (b,s) row.
//  - Phase 1: each lane scans 32 float4 (128 floats) of the row, coalesced
//    (lane + 32*i), recording the last nonzero float4 + its position.
//  - Phase 2: ballot+shfl broadcasts every hit to the warp; for each nonzero
//    component (elem index e, value v) every lane accumulates
//    acc += v * pe[e, lane*4 .. lane*4+3]. Exact sparse contraction.
//  - Write 128 floats (32 float4, one per lane).

#define N_ROWS (8 * 2048)   // B*S
#define M_LEN  4096         // one-hot width
#define M_VEC  (M_LEN / 4)  // 1024 float4 per row
#define D_VEC  (128 / 4)    // 32 float4 per pe row / out row

__global__ __launch_bounds__(256, 8)
void pe_onehot_gather_kernel(const float4* __restrict__ x,
                             const float4* __restrict__ pe,
                             float4* __restrict__ out) {
    const int warp_in_block = threadIdx.x >> 5;
    const int lane = threadIdx.x & 31;
    const int row  = blockIdx.x * 8 + warp_in_block;
    if (row >= N_ROWS) return;

    const float4* xr = x + (size_t)row * M_VEC;

    // ---- Phase 1: scan this lane's 32 float4 slices (coalesced) ----
    float4 hitv = make_float4(0.f, 0.f, 0.f, 0.f);
    int hitpos = -1;
    #pragma unroll 8
    for (int i = 0; i < 32; i++) {
        const int p = lane + 32 * i;
        const float4 v = __ldg(&xr[p]);
        if (v.x != 0.f || v.y != 0.f || v.z != 0.f || v.w != 0.f) {
            hitv = v;
            hitpos = p;
        }
    }

    // ---- Phase 2: broadcast hits, gather + scale pe rows ----
    float4 acc = make_float4(0.f, 0.f, 0.f, 0.f);
    unsigned mask = __ballot_sync(0xffffffffu, hitpos >= 0);
    while (mask) {
        const int src = __ffs(mask) - 1;
        mask &= mask - 1;
        const int   p  = __shfl_sync(0xffffffffu, hitpos, src);
        const float vx = __shfl_sync(0xffffffffu, hitv.x, src);
        const float vy = __shfl_sync(0xffffffffu, hitv.y, src);
        const float vz = __shfl_sync(0xffffffffu, hitv.z, src);
        const float vw = __shfl_sync(0xffffffffu, hitv.w, src);
        const int e = p * 4;  // element index of component .x

        if (vx != 0.f) {
            const float4 pr = __ldg(&pe[(size_t)(e + 0) * D_VEC + lane]);
            acc.x += vx * pr.x; acc.y += vx * pr.y;
            acc.z += vx * pr.z; acc.w += vx * pr.w;
        }
        if (vy != 0.f) {
            const float4 pr = __ldg(&pe[(size_t)(e + 1) * D_VEC + lane]);
            acc.x += vy * pr.x; acc.y += vy * pr.y;
            acc.z += vy * pr.z; acc.w += vy * pr.w;
        }
        if (vz != 0.f) {
            const float4 pr = __ldg(&pe[(size_t)(e + 2) * D_VEC + lane]);
            acc.x += vz * pr.x; acc.y += vz * pr.y;
            acc.z += vz * pr.z; acc.w += vz * pr.w;
        }
        if (vw != 0.f) {
            const float4 pr = __ldg(&pe[(size_t)(e + 3) * D_VEC + lane]);
            acc.x += vw * pr.x; acc.y += vw * pr.y;
            acc.z += vw * pr.z; acc.w += vw * pr.w;
        }
    }

    out[(size_t)row * D_VEC + lane] = acc;
}

extern "C" void kernel_launch(void* const* d_in, const int* in_sizes, int n_in,
                              void* d_out, int out_size) {
    const float4* x  = (const float4*)d_in[0];   // (8,2048,4096) f32
    const float4* pe = (const float4*)d_in[1];   // (4096,128)    f32
    float4* out = (float4*)d_out;                // (8,2048,128)  f32

    const int warps_per_block = 8;               // 256 threads
    const int rows_per_block  = warps_per_block;
    const int grid = (N_ROWS + rows_per_block - 1) / rows_per_block;  // 2048
    pe_onehot_gather_kernel<<<grid, 256>>>(x, pe, out);
}

// round 2
// speedup vs baseline: 1.0462x; 1.0462x over previous
#include <cuda_runtime.h>
#include <cstdint>

// SinusoidPositionEncoding: out[b,s,:] = sum_m x[b,s,m] * pe[m,:]
// x is one-hot over m (4096) => sparse gather-scale.
// x (8,2048,4096) f32, pe (4096,128) f32, out (8,2048,128) f32.
//
// R2 changes vs R1 (46.2us, DRAM 74.3%):
//  - __ldcs (evict-first) on x stream, __stcs on out: keep L2 for pe.
//  - Explicit 8-deep load batches with integer-OR nonzero check:
//    fewer dependent ALU ops between LDG batches -> higher sustained MLP.

#define N_ROWS (8 * 2048)   // B*S
#define M_VEC  1024         // 4096 floats / 4 per row
#define D_VEC  32           // 128 floats / 4

__global__ __launch_bounds__(256)
void pe_onehot_gather_kernel(const uint4* __restrict__ x,
                             const float4* __restrict__ pe,
                             float4* __restrict__ out) {
    const int warp_in_block = threadIdx.x >> 5;
    const int lane = threadIdx.x & 31;
    const int row  = blockIdx.x * 8 + warp_in_block;
    if (row >= N_ROWS) return;

    const uint4* xr = x + (size_t)row * M_VEC;

    // ---- Phase 1: scan 32 float4 per lane, batched 8 loads at a time ----
    uint4 hitv = make_uint4(0u, 0u, 0u, 0u);
    int hitpos = -1;
    #pragma unroll
    for (int g = 0; g < 4; g++) {
        uint4 v[8];
        #pragma unroll
        for (int j = 0; j < 8; j++) {
            v[j] = __ldcs(&xr[lane + 32 * (g * 8 + j)]);   // evict-first stream
        }
        #pragma unroll
        for (int j = 0; j < 8; j++) {
            const unsigned nz = v[j].x | v[j].y | v[j].z | v[j].w;
            if (nz != 0u) {
                hitv = v[j];
                hitpos = lane + 32 * (g * 8 + j);
            }
        }
    }

    // ---- Phase 2: broadcast hits, gather + scale pe rows ----
    float4 acc = make_float4(0.f, 0.f, 0.f, 0.f);
    unsigned mask = __ballot_sync(0xffffffffu, hitpos >= 0);
    while (mask) {
        const int src = __ffs(mask) - 1;
        mask &= mask - 1;
        const int   p  = __shfl_sync(0xffffffffu, hitpos, src);
        const float vx = __uint_as_float(__shfl_sync(0xffffffffu, hitv.x, src));
        const float vy = __uint_as_float(__shfl_sync(0xffffffffu, hitv.y, src));
        const float vz = __uint_as_float(__shfl_sync(0xffffffffu, hitv.z, src));
        const float vw = __uint_as_float(__shfl_sync(0xffffffffu, hitv.w, src));
        const int e = p * 4;  // element index of component .x

        if (__float_as_uint(vx) != 0u) {
            const float4 pr = __ldg(&pe[(size_t)(e + 0) * D_VEC + lane]);
            acc.x += vx * pr.x; acc.y += vx * pr.y;
            acc.z += vx * pr.z; acc.w += vx * pr.w;
        }
        if (__float_as_uint(vy) != 0u) {
            const float4 pr = __ldg(&pe[(size_t)(e + 1) * D_VEC + lane]);
            acc.x += vy * pr.x; acc.y += vy * pr.y;
            acc.z += vy * pr.z; acc.w += vy * pr.w;
        }
        if (__float_as_uint(vz) != 0u) {
            const float4 pr = __ldg(&pe[(size_t)(e + 2) * D_VEC + lane]);
            acc.x += vz * pr.x; acc.y += vz * pr.y;
            acc.z += vz * pr.z; acc.w += vz * pr.w;
        }
        if (__float_as_uint(vw) != 0u) {
            const float4 pr = __ldg(&pe[(size_t)(e + 3) * D_VEC + lane]);
            acc.x += vw * pr.x; acc.y += vw * pr.y;
            acc.z += vw * pr.z; acc.w += vw * pr.w;
        }
    }

    __stcs(&out[(size_t)row * D_VEC + lane], acc);
}

extern "C" void kernel_launch(void* const* d_in, const int* in_sizes, int n_in,
                              void* d_out, int out_size) {
    const uint4*  x  = (const uint4*)d_in[0];    // (8,2048,4096) f32
    const float4* pe = (const float4*)d_in[1];   // (4096,128)    f32
    float4* out = (float4*)d_out;                // (8,2048,128)  f32

    const int grid = N_ROWS / 8;                 // 8 warps (rows) per block
    pe_onehot_gather_kernel<<<grid, 256>>>(x, pe, out);
}

// round 4
// speedup vs baseline: 1.5039x; 1.4375x over previous
#include <cuda_runtime.h>
#include <cstdint>

// SinusoidPositionEncoding: out[b,s,:] = sum_m x[b,s,m] * pe[m,:]
// x is one-hot over m (4096): exactly one nonzero per row.
// => scan the row front-to-back in chunks and EARLY-EXIT at the first hit.
//    Expected x traffic: ~56% of 256MB instead of 100%.
// x (8,2048,4096) f32, pe (4096,128) f32, out (8,2048,128) f32.
// (R4 = R3 resubmitted: prior round failed in the GPU broker, not the kernel.)

#define N_ROWS (8 * 2048)   // B*S = 16384
#define M_VEC  1024         // 4096 floats / 4 per row
#define D_VEC  32           // 128 floats / 4
#define CHUNK_LOADS 4       // 4 x LDG.128 per lane per chunk = 512 floats/warp
#define N_CHUNKS 8          // 8 * 512 = 4096

__global__ __launch_bounds__(256)
void pe_onehot_gather_kernel(const uint4* __restrict__ x,
                             const float4* __restrict__ pe,
                             float4* __restrict__ out) {
    const int warp_in_block = threadIdx.x >> 5;
    const int lane = threadIdx.x & 31;
    const int row  = blockIdx.x * 8 + warp_in_block;
    if (row >= N_ROWS) return;

    const uint4* xr = x + (size_t)row * M_VEC;

    // ---- Phase 1: chunked scan with early exit ----
    uint4 hitv = make_uint4(0u, 0u, 0u, 0u);
    int hitpos = -1;
    unsigned ball = 0u;

    for (int c = 0; c < N_CHUNKS; c++) {
        uint4 v[CHUNK_LOADS];
        const int base = c * (CHUNK_LOADS * 32);
        #pragma unroll
        for (int j = 0; j < CHUNK_LOADS; j++) {
            v[j] = __ldcs(&xr[base + j * 32 + lane]);   // evict-first stream
        }
        #pragma unroll
        for (int j = 0; j < CHUNK_LOADS; j++) {
            if ((v[j].x | v[j].y | v[j].z | v[j].w) != 0u) {
                hitv = v[j];
                hitpos = base + j * 32 + lane;
            }
        }
        ball = __ballot_sync(0xffffffffu, hitpos >= 0);
        if (ball) break;    // one-hot: nothing nonzero after the hit
    }

    // ---- Phase 2: broadcast hit(s), gather + scale pe rows ----
    float4 acc = make_float4(0.f, 0.f, 0.f, 0.f);
    unsigned mask = ball;
    while (mask) {
        const int src = __ffs(mask) - 1;
        mask &= mask - 1;
        const int   p  = __shfl_sync(0xffffffffu, hitpos, src);
        const float vx = __uint_as_float(__shfl_sync(0xffffffffu, hitv.x, src));
        const float vy = __uint_as_float(__shfl_sync(0xffffffffu, hitv.y, src));
        const float vz = __uint_as_float(__shfl_sync(0xffffffffu, hitv.z, src));
        const float vw = __uint_as_float(__shfl_sync(0xffffffffu, hitv.w, src));
        const int e = p * 4;  // element index of component .x

        if (__float_as_uint(vx) != 0u) {
            const float4 pr = __ldg(&pe[(size_t)(e + 0) * D_VEC + lane]);
            acc.x += vx * pr.x; acc.y += vx * pr.y;
            acc.z += vx * pr.z; acc.w += vx * pr.w;
        }
        if (__float_as_uint(vy) != 0u) {
            const float4 pr = __ldg(&pe[(size_t)(e + 1) * D_VEC + lane]);
            acc.x += vy * pr.x; acc.y += vy * pr.y;
            acc.z += vy * pr.z; acc.w += vy * pr.w;
        }
        if (__float_as_uint(vz) != 0u) {
            const float4 pr = __ldg(&pe[(size_t)(e + 2) * D_VEC + lane]);
            acc.x += vz * pr.x; acc.y += vz * pr.y;
            acc.z += vz * pr.z; acc.w += vz * pr.w;
        }
        if (__float_as_uint(vw) != 0u) {
            const float4 pr = __ldg(&pe[(size_t)(e + 3) * D_VEC + lane]);
            acc.x += vw * pr.x; acc.y += vw * pr.y;
            acc.z += vw * pr.z; acc.w += vw * pr.w;
        }
    }

    __stcs(&out[(size_t)row * D_VEC + lane], acc);
}

extern "C" void kernel_launch(void* const* d_in, const int* in_sizes, int n_in,
                              void* d_out, int out_size) {
    const uint4*  x  = (const uint4*)d_in[0];    // (8,2048,4096) f32
    const float4* pe = (const float4*)d_in[1];   // (4096,128)    f32
    float4* out = (float4*)d_out;                // (8,2048,128)  f32

    const int grid = N_ROWS / 8;                 // 8 warps (rows) per block
    pe_onehot_gather_kernel<<<grid, 256>>>(x, pe, out);
}

// round 6
// speedup vs baseline: 1.5172x; 1.0089x over previous
#include <cuda_runtime.h>
#include <cstdint>

// SinusoidPositionEncoding: out[b,s,:] = sum_m x[b,s,m] * pe[m,:]
// x is one-hot over m (4096): early-exit chunked scan (R4, confirmed 56% traffic).
// R6 = R5 resubmitted (prior round died in the GPU broker, not the kernel):
// each warp scans TWO rows concurrently -> 8 LDG.128 in flight per warp
// round-trip instead of 4, and E[max] < E[sum] round-trips. Same bytes, higher rate.
// x (8,2048,4096) f32, pe (4096,128) f32, out (8,2048,128) f32.

#define N_ROWS (8 * 2048)   // 16384
#define M_VEC  1024         // 4096/4 float4 per row
#define D_VEC  32           // 128/4
#define CHUNK_LOADS 4       // 4 x LDG.128 per lane per chunk = 512 floats
#define N_CHUNKS 8

__device__ __forceinline__ void gather_pe(const float4* __restrict__ pe,
                                          unsigned mask, int hitpos, uint4 hitv,
                                          int lane, float4& acc) {
    while (mask) {
        const int src = __ffs(mask) - 1;
        mask &= mask - 1;
        const int   p  = __shfl_sync(0xffffffffu, hitpos, src);
        const float vx = __uint_as_float(__shfl_sync(0xffffffffu, hitv.x, src));
        const float vy = __uint_as_float(__shfl_sync(0xffffffffu, hitv.y, src));
        const float vz = __uint_as_float(__shfl_sync(0xffffffffu, hitv.z, src));
        const float vw = __uint_as_float(__shfl_sync(0xffffffffu, hitv.w, src));
        const int e = p * 4;
        if (__float_as_uint(vx) != 0u) {
            const float4 pr = __ldg(&pe[(size_t)(e + 0) * D_VEC + lane]);
            acc.x += vx * pr.x; acc.y += vx * pr.y; acc.z += vx * pr.z; acc.w += vx * pr.w;
        }
        if (__float_as_uint(vy) != 0u) {
            const float4 pr = __ldg(&pe[(size_t)(e + 1) * D_VEC + lane]);
            acc.x += vy * pr.x; acc.y += vy * pr.y; acc.z += vy * pr.z; acc.w += vy * pr.w;
        }
        if (__float_as_uint(vz) != 0u) {
            const float4 pr = __ldg(&pe[(size_t)(e + 2) * D_VEC + lane]);
            acc.x += vz * pr.x; acc.y += vz * pr.y; acc.z += vz * pr.z; acc.w += vz * pr.w;
        }
        if (__float_as_uint(vw) != 0u) {
            const float4 pr = __ldg(&pe[(size_t)(e + 3) * D_VEC + lane]);
            acc.x += vw * pr.x; acc.y += vw * pr.y; acc.z += vw * pr.z; acc.w += vw * pr.w;
        }
    }
}

__global__ __launch_bounds__(256)
void pe_onehot_gather2_kernel(const uint4* __restrict__ x,
                              const float4* __restrict__ pe,
                              float4* __restrict__ out) {
    const int warp = threadIdx.x >> 5;
    const int lane = threadIdx.x & 31;
    // Block owns 16 rows; warp w owns rows base+w and base+w+8.
    const int rowA = blockIdx.x * 16 + warp;
    const int rowB = rowA + 8;

    const uint4* xA = x + (size_t)rowA * M_VEC;
    const uint4* xB = x + (size_t)rowB * M_VEC;

    uint4 hvA = make_uint4(0u,0u,0u,0u), hvB = make_uint4(0u,0u,0u,0u);
    int hpA = -1, hpB = -1;
    unsigned ballA = 0u, ballB = 0u;

    for (int c = 0; c < N_CHUNKS; c++) {
        const int base = c * (CHUNK_LOADS * 32);
        const bool actA = (ballA == 0u);   // warp-uniform
        const bool actB = (ballB == 0u);   // warp-uniform
        uint4 vA[CHUNK_LOADS], vB[CHUNK_LOADS];

        if (actA) {
            #pragma unroll
            for (int j = 0; j < CHUNK_LOADS; j++)
                vA[j] = __ldcs(&xA[base + j * 32 + lane]);
        }
        if (actB) {
            #pragma unroll
            for (int j = 0; j < CHUNK_LOADS; j++)
                vB[j] = __ldcs(&xB[base + j * 32 + lane]);
        }
        if (actA) {
            #pragma unroll
            for (int j = 0; j < CHUNK_LOADS; j++)
                if ((vA[j].x | vA[j].y | vA[j].z | vA[j].w) != 0u) {
                    hvA = vA[j]; hpA = base + j * 32 + lane;
                }
            ballA = __ballot_sync(0xffffffffu, hpA >= 0);
        }
        if (actB) {
            #pragma unroll
            for (int j = 0; j < CHUNK_LOADS; j++)
                if ((vB[j].x | vB[j].y | vB[j].z | vB[j].w) != 0u) {
                    hvB = vB[j]; hpB = base + j * 32 + lane;
                }
            ballB = __ballot_sync(0xffffffffu, hpB >= 0);
        }
        if (ballA && ballB) break;
    }

    float4 accA = make_float4(0.f,0.f,0.f,0.f);
    float4 accB = make_float4(0.f,0.f,0.f,0.f);
    gather_pe(pe, ballA, hpA, hvA, lane, accA);
    gather_pe(pe, ballB, hpB, hvB, lane, accB);

    __stcs(&out[(size_t)rowA * D_VEC + lane], accA);
    __stcs(&out[(size_t)rowB * D_VEC + lane], accB);
}

extern "C" void kernel_launch(void* const* d_in, const int* in_sizes, int n_in,
                              void* d_out, int out_size) {
    const uint4*  x  = (const uint4*)d_in[0];    // (8,2048,4096) f32
    const float4* pe = (const float4*)d_in[1];   // (4096,128)    f32
    float4* out = (float4*)d_out;                // (8,2048,128)  f32

    const int grid = N_ROWS / 16;                // 1024 blocks, 16 rows each
    pe_onehot_gather2_kernel<<<grid, 256>>>(x, pe, out);
}